// round 13
// baseline (speedup 1.0000x reference)
#include <cuda_runtime.h>
#include <cuda_fp16.h>
#include <cstdint>

#define N_NODES 100000
#define IN_C    128
#define HID_C   64
#define OUT_C   32
#define E_MAX   1600000

// ---------------- scratch ----------------
__device__ float g_dinv[N_NODES];
__device__ int   g_cnt[N_NODES];
__device__ int   g_rp[N_NODES + 1];
__device__ int   g_wptr[N_NODES];
__device__ float2 g_epk[E_MAX];                       // (src bits, weight)
__device__ unsigned g_h1h[(size_t)N_NODES * 32];      // h1 fp16x2 (64 ch)
__device__ unsigned g_o1h[(size_t)N_NODES * 32];      // relu(agg1) fp16x2 (64 ch)
__device__ unsigned g_h2h[(size_t)N_NODES * 16];      // h2 fp16x2 (32 ch)

// ---------------- degree / CSR ----------------
__global__ void k_zero() {
    int i = blockIdx.x * blockDim.x + threadIdx.x;
    if (i < N_NODES) g_cnt[i] = 0;
}

__global__ void k_count(const int* __restrict__ dst, int E) {
    int e0 = (blockIdx.x * blockDim.x + threadIdx.x) * 4;
    if (e0 + 3 < E) {
        int4 d4 = *(const int4*)(dst + e0);
        atomicAdd(&g_cnt[d4.x], 1);
        atomicAdd(&g_cnt[d4.y], 1);
        atomicAdd(&g_cnt[d4.z], 1);
        atomicAdd(&g_cnt[d4.w], 1);
    } else {
        for (int e = e0; e < E; ++e) atomicAdd(&g_cnt[dst[e]], 1);
    }
}

// monolithic scan: one block, 1024 threads; thread t owns cnt[t*100..+99].
// also computes dinv. Replaces scan1/scan2/scan3.
__global__ void __launch_bounds__(1024) k_scan(int E) {
    __shared__ int sh[1024];
    const int t = threadIdx.x;
    const int base = t * 100;
    int s = 0;
    if (base < N_NODES) {
#pragma unroll 5
        for (int i = 0; i < 100; i += 4) {
            int4 v = *(const int4*)&g_cnt[base + i];
            s += v.x + v.y + v.z + v.w;
        }
    }
    sh[t] = s;
    __syncthreads();
#pragma unroll
    for (int off = 1; off < 1024; off <<= 1) {
        int x = (t >= off) ? sh[t - off] : 0;
        __syncthreads();
        sh[t] += x;
        __syncthreads();
    }
    int run = sh[t] - s;                    // exclusive prefix
    if (base < N_NODES) {
#pragma unroll 5
        for (int i = 0; i < 100; i += 4) {
            int idx = base + i;
            int4 cv = *(const int4*)&g_cnt[idx];
            g_dinv[idx + 0] = rsqrtf(1.0f + (float)cv.x);
            g_dinv[idx + 1] = rsqrtf(1.0f + (float)cv.y);
            g_dinv[idx + 2] = rsqrtf(1.0f + (float)cv.z);
            g_dinv[idx + 3] = rsqrtf(1.0f + (float)cv.w);
            int4 r;
            r.x = run;
            r.y = r.x + cv.x;
            r.z = r.y + cv.y;
            r.w = r.z + cv.z;
            run = r.w + cv.w;
            *(int4*)&g_rp[idx]   = r;
            *(int4*)&g_wptr[idx] = r;
        }
    }
    if (t == 0) g_rp[N_NODES] = E;
}

// fill: 4 independent edges/thread, packed (src, weight) payload
__global__ void k_fill(const int* __restrict__ src, const int* __restrict__ dst, int E) {
    int e0 = (blockIdx.x * blockDim.x + threadIdx.x) * 4;
    if (e0 + 3 < E) {
        int4 s4 = *(const int4*)(src + e0);
        int4 d4 = *(const int4*)(dst + e0);
        float w0 = g_dinv[s4.x] * g_dinv[d4.x];
        float w1 = g_dinv[s4.y] * g_dinv[d4.y];
        float w2 = g_dinv[s4.z] * g_dinv[d4.z];
        float w3 = g_dinv[s4.w] * g_dinv[d4.w];
        int p0 = atomicAdd(&g_wptr[d4.x], 1);
        int p1 = atomicAdd(&g_wptr[d4.y], 1);
        int p2 = atomicAdd(&g_wptr[d4.z], 1);
        int p3 = atomicAdd(&g_wptr[d4.w], 1);
        g_epk[p0] = make_float2(__int_as_float(s4.x), w0);
        g_epk[p1] = make_float2(__int_as_float(s4.y), w1);
        g_epk[p2] = make_float2(__int_as_float(s4.z), w2);
        g_epk[p3] = make_float2(__int_as_float(s4.w), w3);
    } else {
        for (int e = e0; e < E; ++e) {
            int s = src[e], d = dst[e];
            float w = g_dinv[s] * g_dinv[d];
            int pos = atomicAdd(&g_wptr[d], 1);
            g_epk[pos] = make_float2(__int_as_float(s), w);
        }
    }
}

// ---------------- GEMM1 v3 (tensor core, register-direct A) --------------
// Block tile M=128, N=64, K=128 in one pass. 8 warps, warp tile m16 x n64.
// A fragments loaded straight from global x (float2 -> half2); only W1 is
// staged in smem (transposed to [n][k] fp16).
#define WS_STR 136    // halves per n row (128 k + 8 pad)
__global__ void __launch_bounds__(256) k_gemm1(const float* __restrict__ x,
                                               const float* __restrict__ W) {
    __shared__ __half ws[64 * WS_STR];    // 17.4 KB
    const int t = threadIdx.x;
    const int row0 = blockIdx.x * 128;
    const int w    = t >> 5;
    const int lane = t & 31;
    const int g    = lane >> 2;          // 0..7
    const int tq   = lane & 3;           // 0..3
    const int arow = w * 16;

    // load W1 [128][64] -> ws[n][k] fp16 (transposed)
#pragma unroll
    for (int i = 0; i < 8; ++i) {
        int idx = t + i * 256;           // float4 index, 0..2047
        int k = idx >> 4;                // 0..127
        int q = idx & 15;                // n-group of 4
        float4 v = ((const float4*)W)[idx];
        ws[(q * 4 + 0) * WS_STR + k] = __float2half(v.x);
        ws[(q * 4 + 1) * WS_STR + k] = __float2half(v.y);
        ws[(q * 4 + 2) * WS_STR + k] = __float2half(v.z);
        ws[(q * 4 + 3) * WS_STR + k] = __float2half(v.w);
    }
    __syncthreads();

    const int r0 = row0 + arow + g;
    const int r1 = r0 + 8;
    const bool ok0 = r0 < N_NODES;
    const bool ok1 = r1 < N_NODES;
    const float* xr0 = x + (size_t)r0 * IN_C;
    const float* xr1 = x + (size_t)r1 * IN_C;
    const float2 z2 = make_float2(0.f, 0.f);

    float acc[8][4];
#pragma unroll
    for (int i = 0; i < 8; ++i)
#pragma unroll
        for (int j = 0; j < 4; ++j) acc[i][j] = 0.f;

#pragma unroll
    for (int ks = 0; ks < 128; ks += 16) {
        const int c0 = ks + tq * 2;
        float2 a0 = ok0 ? *(const float2*)(xr0 + c0)     : z2;
        float2 a1 = ok1 ? *(const float2*)(xr1 + c0)     : z2;
        float2 a2 = ok0 ? *(const float2*)(xr0 + c0 + 8) : z2;
        float2 a3 = ok1 ? *(const float2*)(xr1 + c0 + 8) : z2;
        __half2 h0 = __floats2half2_rn(a0.x, a0.y);
        __half2 h1 = __floats2half2_rn(a1.x, a1.y);
        __half2 h2 = __floats2half2_rn(a2.x, a2.y);
        __half2 h3 = __floats2half2_rn(a3.x, a3.y);
        unsigned A0 = *(unsigned*)&h0;
        unsigned A1 = *(unsigned*)&h1;
        unsigned A2 = *(unsigned*)&h2;
        unsigned A3 = *(unsigned*)&h3;
#pragma unroll
        for (int i = 0; i < 8; ++i) {
            unsigned B0 = *(const unsigned*)&ws[(i * 8 + g) * WS_STR + c0];
            unsigned B1 = *(const unsigned*)&ws[(i * 8 + g) * WS_STR + c0 + 8];
            asm volatile(
                "mma.sync.aligned.m16n8k16.row.col.f32.f16.f16.f32 "
                "{%0,%1,%2,%3},{%4,%5,%6,%7},{%8,%9},{%0,%1,%2,%3};"
                : "+f"(acc[i][0]), "+f"(acc[i][1]), "+f"(acc[i][2]), "+f"(acc[i][3])
                : "r"(A0), "r"(A1), "r"(A2), "r"(A3), "r"(B0), "r"(B1));
        }
    }

    // store: rows r0/r1, col pair tq of n-tile i
#pragma unroll
    for (int i = 0; i < 8; ++i) {
        if (ok0) {
            __half2 h = __floats2half2_rn(acc[i][0], acc[i][1]);
            g_h1h[(size_t)r0 * 32 + i * 4 + tq] = *(unsigned*)&h;
        }
        if (ok1) {
            __half2 h = __floats2half2_rn(acc[i][2], acc[i][3]);
            g_h1h[(size_t)r1 * 32 + i * 4 + tq] = *(unsigned*)&h;
        }
    }
}

// ---------------- aggregate layer 1: full warp/node, unroll 8 ------------
__global__ void __launch_bounds__(256) k_agg1(const float* __restrict__ b1) {
    int node = blockIdx.x * 8 + (threadIdx.x >> 5);
    if (node >= N_NODES) return;
    int lane = threadIdx.x & 31;
    int beg = g_rp[node], end = g_rp[node + 1];
    float d = g_dinv[node];
    float dd = d * d;

    unsigned sp = g_h1h[(unsigned)node * 32u + lane];
    float2 sv = __half22float2(*(__half2*)&sp);
    float2 bb = *(const float2*)&b1[lane * 2];
    float ax = bb.x + sv.x * dd;
    float ay = bb.y + sv.y * dd;

    int j = beg;
    if ((j & 1) && j < end) {
        float2 p = g_epk[j];
        unsigned v = g_h1h[(unsigned)__float_as_int(p.x) * 32u + lane];
        float2 f = __half22float2(*(__half2*)&v);
        ax += p.y * f.x; ay += p.y * f.y;
        ++j;
    }
    for (; j + 7 < end; j += 8) {
        float4 e0 = *(const float4*)&g_epk[j];
        float4 e1 = *(const float4*)&g_epk[j + 2];
        float4 e2 = *(const float4*)&g_epk[j + 4];
        float4 e3 = *(const float4*)&g_epk[j + 6];
        unsigned v0 = g_h1h[(unsigned)__float_as_int(e0.x) * 32u + lane];
        unsigned v1 = g_h1h[(unsigned)__float_as_int(e0.z) * 32u + lane];
        unsigned v2 = g_h1h[(unsigned)__float_as_int(e1.x) * 32u + lane];
        unsigned v3 = g_h1h[(unsigned)__float_as_int(e1.z) * 32u + lane];
        unsigned v4 = g_h1h[(unsigned)__float_as_int(e2.x) * 32u + lane];
        unsigned v5 = g_h1h[(unsigned)__float_as_int(e2.z) * 32u + lane];
        unsigned v6 = g_h1h[(unsigned)__float_as_int(e3.x) * 32u + lane];
        unsigned v7 = g_h1h[(unsigned)__float_as_int(e3.z) * 32u + lane];
        float2 f0 = __half22float2(*(__half2*)&v0);
        float2 f1 = __half22float2(*(__half2*)&v1);
        float2 f2 = __half22float2(*(__half2*)&v2);
        float2 f3 = __half22float2(*(__half2*)&v3);
        float2 f4 = __half22float2(*(__half2*)&v4);
        float2 f5 = __half22float2(*(__half2*)&v5);
        float2 f6 = __half22float2(*(__half2*)&v6);
        float2 f7 = __half22float2(*(__half2*)&v7);
        ax += e0.y * f0.x + e0.w * f1.x + e1.y * f2.x + e1.w * f3.x
            + e2.y * f4.x + e2.w * f5.x + e3.y * f6.x + e3.w * f7.x;
        ay += e0.y * f0.y + e0.w * f1.y + e1.y * f2.y + e1.w * f3.y
            + e2.y * f4.y + e2.w * f5.y + e3.y * f6.y + e3.w * f7.y;
    }
    for (; j + 1 < end; j += 2) {
        float4 e0 = *(const float4*)&g_epk[j];
        unsigned v0 = g_h1h[(unsigned)__float_as_int(e0.x) * 32u + lane];
        unsigned v1 = g_h1h[(unsigned)__float_as_int(e0.z) * 32u + lane];
        float2 f0 = __half22float2(*(__half2*)&v0);
        float2 f1 = __half22float2(*(__half2*)&v1);
        ax += e0.y * f0.x + e0.w * f1.x;
        ay += e0.y * f0.y + e0.w * f1.y;
    }
    if (j < end) {
        float2 p = g_epk[j];
        unsigned v = g_h1h[(unsigned)__float_as_int(p.x) * 32u + lane];
        float2 f = __half22float2(*(__half2*)&v);
        ax += p.y * f.x; ay += p.y * f.y;
    }

    __half2 hh = __floats2half2_rn(fmaxf(ax, 0.f), fmaxf(ay, 0.f));
    g_o1h[(unsigned)node * 32u + lane] = *(unsigned*)&hh;
}

// ---------------- GEMM2: h2[N,32] = o1[N,64] @ W2[64,32] -> fp16 ---------
__global__ void __launch_bounds__(256) k_gemm2(const float* __restrict__ W) {
    __shared__ float xs[64 * 64];
    __shared__ float ws[64 * 32];
    const int tid  = threadIdx.x;
    const int row0 = blockIdx.x * 64;

    const float4* Wv  = (const float4*)W;
    float4*       wsv = (float4*)ws;
#pragma unroll
    for (int i = 0; i < 2; ++i) wsv[tid + i * 256] = Wv[tid + i * 256];

    int nrows = N_NODES - row0; if (nrows > 64) nrows = 64;
    for (int i = tid; i < nrows * 8; i += 256) {
        int r = i >> 3, q = i & 7;
        uint4 v = *(const uint4*)&g_o1h[(size_t)(row0 + r) * 32 + q * 4];
        float2 f0 = __half22float2(*(__half2*)&v.x);
        float2 f1 = __half22float2(*(__half2*)&v.y);
        float2 f2 = __half22float2(*(__half2*)&v.z);
        float2 f3 = __half22float2(*(__half2*)&v.w);
        float* p = &xs[r * 64 + q * 8];
        *(float4*)p       = make_float4(f0.x, f0.y, f1.x, f1.y);
        *(float4*)(p + 4) = make_float4(f2.x, f2.y, f3.x, f3.y);
    }
    __syncthreads();

    const int tx = tid & 7;
    const int ty = tid >> 3;
    const int c  = tx * 4;
    float acc[2][4] = {};
#pragma unroll 4
    for (int k = 0; k < 64; ++k) {
        float4 b = *(const float4*)&ws[k * 32 + c];
#pragma unroll
        for (int i = 0; i < 2; ++i) {
            float a = xs[(ty * 2 + i) * 64 + k];
            acc[i][0] += a * b.x; acc[i][1] += a * b.y;
            acc[i][2] += a * b.z; acc[i][3] += a * b.w;
        }
    }
#pragma unroll
    for (int i = 0; i < 2; ++i) {
        int r = row0 + ty * 2 + i;
        if (r < N_NODES) {
            __half2 h0 = __floats2half2_rn(acc[i][0], acc[i][1]);
            __half2 h1 = __floats2half2_rn(acc[i][2], acc[i][3]);
            *(uint2*)&g_h2h[(size_t)r * 16 + tx * 2] =
                make_uint2(*(unsigned*)&h0, *(unsigned*)&h1);
        }
    }
}

// ---------------- aggregate layer 2 (half-warp/edge, unroll 2) -> out ----
__global__ void __launch_bounds__(256) k_agg2(const float* __restrict__ b2,
                                              float* __restrict__ out) {
    int node = blockIdx.x * 8 + (threadIdx.x >> 5);
    if (node >= N_NODES) return;
    int lane = threadIdx.x & 31;
    int c  = lane & 15;
    int eo = lane >> 4;

    int beg = g_rp[node], end = g_rp[node + 1];
    float ax = 0.f, ay = 0.f;

    int j = beg + eo;
    for (; j + 3 < end; j += 4) {
        float2 p0 = g_epk[j];
        float2 p1 = g_epk[j + 2];
        unsigned v0 = g_h2h[(unsigned)__float_as_int(p0.x) * 16u + c];
        unsigned v1 = g_h2h[(unsigned)__float_as_int(p1.x) * 16u + c];
        float2 f0 = __half22float2(*(__half2*)&v0);
        float2 f1 = __half22float2(*(__half2*)&v1);
        ax += p0.y * f0.x + p1.y * f1.x;
        ay += p0.y * f0.y + p1.y * f1.y;
    }
    for (; j < end; j += 2) {
        float2 p = g_epk[j];
        unsigned v = g_h2h[(unsigned)__float_as_int(p.x) * 16u + c];
        float2 f = __half22float2(*(__half2*)&v);
        ax += p.y * f.x; ay += p.y * f.y;
    }

    ax += __shfl_xor_sync(0xffffffffu, ax, 16);
    ay += __shfl_xor_sync(0xffffffffu, ay, 16);

    if (eo == 0) {
        float d = g_dinv[node];
        float dd = d * d;
        unsigned sp = g_h2h[(unsigned)node * 16u + c];
        float2 sv = __half22float2(*(__half2*)&sp);
        float2 bb = *(const float2*)&b2[c * 2];
        ax += bb.x + sv.x * dd;
        ay += bb.y + sv.y * dd;
        *(float2*)&out[(size_t)node * OUT_C + c * 2] = make_float2(ax, ay);
    }
}

// ---------------- launch: serial; gemm1 stays in profiled slot 4 ---------
extern "C" void kernel_launch(void* const* d_in, const int* in_sizes, int n_in,
                              void* d_out, int out_size) {
    const float* x  = (const float*)d_in[0];
    const int*   ei = (const int*)  d_in[1];
    const float* W1 = (const float*)d_in[2];
    const float* b1 = (const float*)d_in[3];
    const float* W2 = (const float*)d_in[4];
    const float* b2 = (const float*)d_in[5];
    float*       out = (float*)d_out;

    const int E   = in_sizes[1] / 2;
    const int* src = ei;
    const int* dst = ei + E;

    k_zero <<<(N_NODES + 255) / 256, 256>>>();
    k_count<<<(E / 4 + 255) / 256, 256>>>(dst, E);
    k_scan <<<1, 1024>>>(E);
    k_gemm1<<<(N_NODES + 127) / 128, 256>>>(x, W1);   // slot 4: profiled launch
    k_fill <<<(E / 4 + 255) / 256, 256>>>(src, dst, E);

    k_agg1 <<<(N_NODES + 7) / 8, 256>>>(b1);
    k_gemm2<<<(N_NODES + 63) / 64, 256>>>(W2);
    k_agg2 <<<(N_NODES + 7) / 8, 256>>>(b2, out);
}

// round 14
// speedup vs baseline: 1.5949x; 1.5949x over previous
#include <cuda_runtime.h>
#include <cuda_fp16.h>
#include <cstdint>

#define N_NODES 100000
#define IN_C    128
#define HID_C   64
#define OUT_C   32
#define E_MAX   1600000
#define NB_SCAN ((N_NODES + 255) / 256)   // 391

// ---------------- scratch ----------------
__device__ float g_dinv[N_NODES];
__device__ int   g_cnt[N_NODES];
__device__ int   g_rp[N_NODES + 1];
__device__ int   g_wptr[N_NODES];
__device__ int   g_bsum[NB_SCAN];
__device__ float2 g_epk[E_MAX];                       // (src bits, weight)
__device__ unsigned g_h1h[(size_t)N_NODES * 32];      // h1 fp16x2 (64 ch)
__device__ unsigned g_o1h[(size_t)N_NODES * 32];      // relu(agg1) fp16x2 (64 ch)
__device__ unsigned g_h2h[(size_t)N_NODES * 16];      // h2 fp16x2 (32 ch)

// ---------------- degree / CSR (proven 391-block chain) ----------------
__global__ void k_zero() {
    int i = blockIdx.x * blockDim.x + threadIdx.x;
    if (i < N_NODES) g_cnt[i] = 0;
}

__global__ void k_count(const int* __restrict__ dst, int E) {
    int e0 = (blockIdx.x * blockDim.x + threadIdx.x) * 4;
    if (e0 + 3 < E) {
        int4 d4 = *(const int4*)(dst + e0);
        atomicAdd(&g_cnt[d4.x], 1);
        atomicAdd(&g_cnt[d4.y], 1);
        atomicAdd(&g_cnt[d4.z], 1);
        atomicAdd(&g_cnt[d4.w], 1);
    } else {
        for (int e = e0; e < E; ++e) atomicAdd(&g_cnt[dst[e]], 1);
    }
}

__global__ void k_scan1() {
    __shared__ int sh[256];
    int t = threadIdx.x;
    int i = blockIdx.x * 256 + t;
    int v = (i < N_NODES) ? g_cnt[i] : 0;
    if (i < N_NODES) g_dinv[i] = rsqrtf(1.0f + (float)v);
    sh[t] = v;
    __syncthreads();
#pragma unroll
    for (int off = 1; off < 256; off <<= 1) {
        int x = (t >= off) ? sh[t - off] : 0;
        __syncthreads();
        sh[t] += x;
        __syncthreads();
    }
    if (i < N_NODES) g_rp[i] = sh[t] - v;
    if (t == 255) g_bsum[blockIdx.x] = sh[255];
}

__global__ void k_scan2() {
    __shared__ int sh[512];
    int t = threadIdx.x;
    int v = (t < NB_SCAN) ? g_bsum[t] : 0;
    sh[t] = v;
    __syncthreads();
#pragma unroll
    for (int off = 1; off < 512; off <<= 1) {
        int x = (t >= off) ? sh[t - off] : 0;
        __syncthreads();
        sh[t] += x;
        __syncthreads();
    }
    if (t < NB_SCAN) g_bsum[t] = sh[t] - v;
}

__global__ void k_scan3(int E) {
    int i = blockIdx.x * blockDim.x + threadIdx.x;
    if (i < N_NODES) {
        int v = g_rp[i] + g_bsum[i >> 8];
        g_rp[i]   = v;
        g_wptr[i] = v;
    }
    if (i == 0) g_rp[N_NODES] = E;
}

// fill: 4 independent edges/thread, packed (src, weight) payload
__global__ void k_fill(const int* __restrict__ src, const int* __restrict__ dst, int E) {
    int e0 = (blockIdx.x * blockDim.x + threadIdx.x) * 4;
    if (e0 + 3 < E) {
        int4 s4 = *(const int4*)(src + e0);
        int4 d4 = *(const int4*)(dst + e0);
        float w0 = g_dinv[s4.x] * g_dinv[d4.x];
        float w1 = g_dinv[s4.y] * g_dinv[d4.y];
        float w2 = g_dinv[s4.z] * g_dinv[d4.z];
        float w3 = g_dinv[s4.w] * g_dinv[d4.w];
        int p0 = atomicAdd(&g_wptr[d4.x], 1);
        int p1 = atomicAdd(&g_wptr[d4.y], 1);
        int p2 = atomicAdd(&g_wptr[d4.z], 1);
        int p3 = atomicAdd(&g_wptr[d4.w], 1);
        g_epk[p0] = make_float2(__int_as_float(s4.x), w0);
        g_epk[p1] = make_float2(__int_as_float(s4.y), w1);
        g_epk[p2] = make_float2(__int_as_float(s4.z), w2);
        g_epk[p3] = make_float2(__int_as_float(s4.w), w3);
    } else {
        for (int e = e0; e < E; ++e) {
            int s = src[e], d = dst[e];
            float w = g_dinv[s] * g_dinv[d];
            int pos = atomicAdd(&g_wptr[d], 1);
            g_epk[pos] = make_float2(__int_as_float(s), w);
        }
    }
}

// ---------------- GEMM1 v3 (tensor core, register-direct A) --------------
#define WS_STR 136    // halves per n row (128 k + 8 pad)
__global__ void __launch_bounds__(256) k_gemm1(const float* __restrict__ x,
                                               const float* __restrict__ W) {
    __shared__ __half ws[64 * WS_STR];    // 17.4 KB
    const int t = threadIdx.x;
    const int row0 = blockIdx.x * 128;
    const int w    = t >> 5;
    const int lane = t & 31;
    const int g    = lane >> 2;          // 0..7
    const int tq   = lane & 3;           // 0..3
    const int arow = w * 16;

    // load W1 [128][64] -> ws[n][k] fp16 (transposed)
#pragma unroll
    for (int i = 0; i < 8; ++i) {
        int idx = t + i * 256;           // float4 index, 0..2047
        int k = idx >> 4;                // 0..127
        int q = idx & 15;                // n-group of 4
        float4 v = ((const float4*)W)[idx];
        ws[(q * 4 + 0) * WS_STR + k] = __float2half(v.x);
        ws[(q * 4 + 1) * WS_STR + k] = __float2half(v.y);
        ws[(q * 4 + 2) * WS_STR + k] = __float2half(v.z);
        ws[(q * 4 + 3) * WS_STR + k] = __float2half(v.w);
    }
    __syncthreads();

    const int r0 = row0 + arow + g;
    const int r1 = r0 + 8;
    const bool ok0 = r0 < N_NODES;
    const bool ok1 = r1 < N_NODES;
    const float* xr0 = x + (size_t)r0 * IN_C;
    const float* xr1 = x + (size_t)r1 * IN_C;
    const float2 z2 = make_float2(0.f, 0.f);

    float acc[8][4];
#pragma unroll
    for (int i = 0; i < 8; ++i)
#pragma unroll
        for (int j = 0; j < 4; ++j) acc[i][j] = 0.f;

#pragma unroll
    for (int ks = 0; ks < 128; ks += 16) {
        const int c0 = ks + tq * 2;
        float2 a0 = ok0 ? *(const float2*)(xr0 + c0)     : z2;
        float2 a1 = ok1 ? *(const float2*)(xr1 + c0)     : z2;
        float2 a2 = ok0 ? *(const float2*)(xr0 + c0 + 8) : z2;
        float2 a3 = ok1 ? *(const float2*)(xr1 + c0 + 8) : z2;
        __half2 h0 = __floats2half2_rn(a0.x, a0.y);
        __half2 h1 = __floats2half2_rn(a1.x, a1.y);
        __half2 h2 = __floats2half2_rn(a2.x, a2.y);
        __half2 h3 = __floats2half2_rn(a3.x, a3.y);
        unsigned A0 = *(unsigned*)&h0;
        unsigned A1 = *(unsigned*)&h1;
        unsigned A2 = *(unsigned*)&h2;
        unsigned A3 = *(unsigned*)&h3;
#pragma unroll
        for (int i = 0; i < 8; ++i) {
            unsigned B0 = *(const unsigned*)&ws[(i * 8 + g) * WS_STR + c0];
            unsigned B1 = *(const unsigned*)&ws[(i * 8 + g) * WS_STR + c0 + 8];
            asm volatile(
                "mma.sync.aligned.m16n8k16.row.col.f32.f16.f16.f32 "
                "{%0,%1,%2,%3},{%4,%5,%6,%7},{%8,%9},{%0,%1,%2,%3};"
                : "+f"(acc[i][0]), "+f"(acc[i][1]), "+f"(acc[i][2]), "+f"(acc[i][3])
                : "r"(A0), "r"(A1), "r"(A2), "r"(A3), "r"(B0), "r"(B1));
        }
    }

#pragma unroll
    for (int i = 0; i < 8; ++i) {
        if (ok0) {
            __half2 h = __floats2half2_rn(acc[i][0], acc[i][1]);
            g_h1h[(size_t)r0 * 32 + i * 4 + tq] = *(unsigned*)&h;
        }
        if (ok1) {
            __half2 h = __floats2half2_rn(acc[i][2], acc[i][3]);
            g_h1h[(size_t)r1 * 32 + i * 4 + tq] = *(unsigned*)&h;
        }
    }
}

// ---------------- aggregate layer 1: full warp/node, unroll 8 ------------
__global__ void __launch_bounds__(256) k_agg1(const float* __restrict__ b1) {
    int node = blockIdx.x * 8 + (threadIdx.x >> 5);
    if (node >= N_NODES) return;
    int lane = threadIdx.x & 31;
    int beg = g_rp[node], end = g_rp[node + 1];
    float d = g_dinv[node];
    float dd = d * d;

    unsigned sp = g_h1h[(unsigned)node * 32u + lane];
    float2 sv = __half22float2(*(__half2*)&sp);
    float2 bb = *(const float2*)&b1[lane * 2];
    float ax = bb.x + sv.x * dd;
    float ay = bb.y + sv.y * dd;

    int j = beg;
    if ((j & 1) && j < end) {
        float2 p = g_epk[j];
        unsigned v = g_h1h[(unsigned)__float_as_int(p.x) * 32u + lane];
        float2 f = __half22float2(*(__half2*)&v);
        ax += p.y * f.x; ay += p.y * f.y;
        ++j;
    }
    for (; j + 7 < end; j += 8) {
        float4 e0 = *(const float4*)&g_epk[j];
        float4 e1 = *(const float4*)&g_epk[j + 2];
        float4 e2 = *(const float4*)&g_epk[j + 4];
        float4 e3 = *(const float4*)&g_epk[j + 6];
        unsigned v0 = g_h1h[(unsigned)__float_as_int(e0.x) * 32u + lane];
        unsigned v1 = g_h1h[(unsigned)__float_as_int(e0.z) * 32u + lane];
        unsigned v2 = g_h1h[(unsigned)__float_as_int(e1.x) * 32u + lane];
        unsigned v3 = g_h1h[(unsigned)__float_as_int(e1.z) * 32u + lane];
        unsigned v4 = g_h1h[(unsigned)__float_as_int(e2.x) * 32u + lane];
        unsigned v5 = g_h1h[(unsigned)__float_as_int(e2.z) * 32u + lane];
        unsigned v6 = g_h1h[(unsigned)__float_as_int(e3.x) * 32u + lane];
        unsigned v7 = g_h1h[(unsigned)__float_as_int(e3.z) * 32u + lane];
        float2 f0 = __half22float2(*(__half2*)&v0);
        float2 f1 = __half22float2(*(__half2*)&v1);
        float2 f2 = __half22float2(*(__half2*)&v2);
        float2 f3 = __half22float2(*(__half2*)&v3);
        float2 f4 = __half22float2(*(__half2*)&v4);
        float2 f5 = __half22float2(*(__half2*)&v5);
        float2 f6 = __half22float2(*(__half2*)&v6);
        float2 f7 = __half22float2(*(__half2*)&v7);
        ax += e0.y * f0.x + e0.w * f1.x + e1.y * f2.x + e1.w * f3.x
            + e2.y * f4.x + e2.w * f5.x + e3.y * f6.x + e3.w * f7.x;
        ay += e0.y * f0.y + e0.w * f1.y + e1.y * f2.y + e1.w * f3.y
            + e2.y * f4.y + e2.w * f5.y + e3.y * f6.y + e3.w * f7.y;
    }
    for (; j + 1 < end; j += 2) {
        float4 e0 = *(const float4*)&g_epk[j];
        unsigned v0 = g_h1h[(unsigned)__float_as_int(e0.x) * 32u + lane];
        unsigned v1 = g_h1h[(unsigned)__float_as_int(e0.z) * 32u + lane];
        float2 f0 = __half22float2(*(__half2*)&v0);
        float2 f1 = __half22float2(*(__half2*)&v1);
        ax += e0.y * f0.x + e0.w * f1.x;
        ay += e0.y * f0.y + e0.w * f1.y;
    }
    if (j < end) {
        float2 p = g_epk[j];
        unsigned v = g_h1h[(unsigned)__float_as_int(p.x) * 32u + lane];
        float2 f = __half22float2(*(__half2*)&v);
        ax += p.y * f.x; ay += p.y * f.y;
    }

    __half2 hh = __floats2half2_rn(fmaxf(ax, 0.f), fmaxf(ay, 0.f));
    g_o1h[(unsigned)node * 32u + lane] = *(unsigned*)&hh;
}

// ---------------- GEMM2: h2[N,32] = o1[N,64] @ W2[64,32] -> fp16 ---------
__global__ void __launch_bounds__(256) k_gemm2(const float* __restrict__ W) {
    __shared__ float xs[64 * 64];
    __shared__ float ws[64 * 32];
    const int tid  = threadIdx.x;
    const int row0 = blockIdx.x * 64;

    const float4* Wv  = (const float4*)W;
    float4*       wsv = (float4*)ws;
#pragma unroll
    for (int i = 0; i < 2; ++i) wsv[tid + i * 256] = Wv[tid + i * 256];

    int nrows = N_NODES - row0; if (nrows > 64) nrows = 64;
    for (int i = tid; i < nrows * 8; i += 256) {
        int r = i >> 3, q = i & 7;
        uint4 v = *(const uint4*)&g_o1h[(size_t)(row0 + r) * 32 + q * 4];
        float2 f0 = __half22float2(*(__half2*)&v.x);
        float2 f1 = __half22float2(*(__half2*)&v.y);
        float2 f2 = __half22float2(*(__half2*)&v.z);
        float2 f3 = __half22float2(*(__half2*)&v.w);
        float* p = &xs[r * 64 + q * 8];
        *(float4*)p       = make_float4(f0.x, f0.y, f1.x, f1.y);
        *(float4*)(p + 4) = make_float4(f2.x, f2.y, f3.x, f3.y);
    }
    __syncthreads();

    const int tx = tid & 7;
    const int ty = tid >> 3;
    const int c  = tx * 4;
    float acc[2][4] = {};
#pragma unroll 4
    for (int k = 0; k < 64; ++k) {
        float4 b = *(const float4*)&ws[k * 32 + c];
#pragma unroll
        for (int i = 0; i < 2; ++i) {
            float a = xs[(ty * 2 + i) * 64 + k];
            acc[i][0] += a * b.x; acc[i][1] += a * b.y;
            acc[i][2] += a * b.z; acc[i][3] += a * b.w;
        }
    }
#pragma unroll
    for (int i = 0; i < 2; ++i) {
        int r = row0 + ty * 2 + i;
        if (r < N_NODES) {
            __half2 h0 = __floats2half2_rn(acc[i][0], acc[i][1]);
            __half2 h1 = __floats2half2_rn(acc[i][2], acc[i][3]);
            *(uint2*)&g_h2h[(size_t)r * 16 + tx * 2] =
                make_uint2(*(unsigned*)&h0, *(unsigned*)&h1);
        }
    }
}

// ---------------- aggregate layer 2 (half-warp/edge, unroll 2) -> out ----
__global__ void __launch_bounds__(256) k_agg2(const float* __restrict__ b2,
                                              float* __restrict__ out) {
    int node = blockIdx.x * 8 + (threadIdx.x >> 5);
    if (node >= N_NODES) return;
    int lane = threadIdx.x & 31;
    int c  = lane & 15;
    int eo = lane >> 4;

    int beg = g_rp[node], end = g_rp[node + 1];
    float ax = 0.f, ay = 0.f;

    int j = beg + eo;
    for (; j + 3 < end; j += 4) {
        float2 p0 = g_epk[j];
        float2 p1 = g_epk[j + 2];
        unsigned v0 = g_h2h[(unsigned)__float_as_int(p0.x) * 16u + c];
        unsigned v1 = g_h2h[(unsigned)__float_as_int(p1.x) * 16u + c];
        float2 f0 = __half22float2(*(__half2*)&v0);
        float2 f1 = __half22float2(*(__half2*)&v1);
        ax += p0.y * f0.x + p1.y * f1.x;
        ay += p0.y * f0.y + p1.y * f1.y;
    }
    for (; j < end; j += 2) {
        float2 p = g_epk[j];
        unsigned v = g_h2h[(unsigned)__float_as_int(p.x) * 16u + c];
        float2 f = __half22float2(*(__half2*)&v);
        ax += p.y * f.x; ay += p.y * f.y;
    }

    ax += __shfl_xor_sync(0xffffffffu, ax, 16);
    ay += __shfl_xor_sync(0xffffffffu, ay, 16);

    if (eo == 0) {
        float d = g_dinv[node];
        float dd = d * d;
        unsigned sp = g_h2h[(unsigned)node * 16u + c];
        float2 sv = __half22float2(*(__half2*)&sp);
        float2 bb = *(const float2*)&b2[c * 2];
        ax += bb.x + sv.x * dd;
        ay += bb.y + sv.y * dd;
        *(float2*)&out[(size_t)node * OUT_C + c * 2] = make_float2(ax, ay);
    }
}

// ---------------- launch: serial; gemm1 in profiled slot 4 ---------------
extern "C" void kernel_launch(void* const* d_in, const int* in_sizes, int n_in,
                              void* d_out, int out_size) {
    const float* x  = (const float*)d_in[0];
    const int*   ei = (const int*)  d_in[1];
    const float* W1 = (const float*)d_in[2];
    const float* b1 = (const float*)d_in[3];
    const float* W2 = (const float*)d_in[4];
    const float* b2 = (const float*)d_in[5];
    float*       out = (float*)d_out;

    const int E   = in_sizes[1] / 2;
    const int* src = ei;
    const int* dst = ei + E;

    k_zero <<<(N_NODES + 255) / 256, 256>>>();
    k_count<<<(E / 4 + 255) / 256, 256>>>(dst, E);
    k_scan1<<<NB_SCAN, 256>>>();
    k_gemm1<<<(N_NODES + 127) / 128, 256>>>(x, W1);   // slot 4: profiled launch
    k_scan2<<<1, 512>>>();
    k_scan3<<<(N_NODES + 255) / 256, 256>>>(E);
    k_fill <<<(E / 4 + 255) / 256, 256>>>(src, dst, E);

    k_agg1 <<<(N_NODES + 7) / 8, 256>>>(b1);
    k_gemm2<<<(N_NODES + 63) / 64, 256>>>(W2);
    k_agg2 <<<(N_NODES + 7) / 8, 256>>>(b2, out);
}